// round 8
// baseline (speedup 1.0000x reference)
#include <cuda_runtime.h>
#include <cuda_fp16.h>
#include <cstddef>
#include <cstdint>
#include <math.h>

// ---------------------------------------------------------------------------
// Problem dims
// ---------------------------------------------------------------------------
#define BBATCH 2
#define TT   2048
#define HID  2048
#define KVD  1024
#define VOC  32000
#define MTOT (BBATCH * TT)   // 4096

// ---------------------------------------------------------------------------
// Scratch (plain row-major fp16; no permutation)
// ---------------------------------------------------------------------------
__device__ __align__(256) __half g_hp [(size_t)MTOT * HID];
__device__ __align__(256) __half g_ep [(size_t)MTOT * HID];
__device__ __align__(256) __half g_wqp[(size_t)KVD * HID];
__device__ __align__(256) __half g_wkp[(size_t)KVD * HID];
__device__ __align__(256) __half g_wvp[(size_t)KVD * HID];
__device__ __align__(256) __half g_wop[(size_t)VOC * KVD];
__device__ __align__(256) __half g_q  [(size_t)MTOT * KVD];
__device__ __align__(256) __half g_k  [(size_t)MTOT * KVD];
__device__ __align__(256) __half g_vT [(size_t)KVD * MTOT];     // [KVD, B*T]
__device__ __align__(256) __half g_ctx[(size_t)MTOT * KVD];
__device__ __align__(256) __half g_attn[(size_t)MTOT * TT];
__device__ __align__(256) float  g_scores[(size_t)BBATCH * TT * TT];

// ---------------------------------------------------------------------------
// Helpers
// ---------------------------------------------------------------------------
__device__ __forceinline__ uint32_t s2u(const void* p) {
    uint32_t a;
    asm("{ .reg .u64 t; cvta.to.shared.u64 t, %1; cvt.u32.u64 %0, t; }"
        : "=r"(a) : "l"(p));
    return a;
}

__device__ __forceinline__ void cpasync16(uint32_t dst, const void* src) {
    asm volatile("cp.async.cg.shared.global [%0], [%1], 16;"
                 :: "r"(dst), "l"(src));
}
#define CP_COMMIT() asm volatile("cp.async.commit_group;" ::: "memory")
#define CP_WAIT1()  asm volatile("cp.async.wait_group 1;"  ::: "memory")

__device__ __forceinline__ void ldsm4(uint32_t* r, uint32_t a) {
    asm volatile("ldmatrix.sync.aligned.m8n8.x4.shared.b16 {%0,%1,%2,%3}, [%4];"
                 : "=r"(r[0]), "=r"(r[1]), "=r"(r[2]), "=r"(r[3]) : "r"(a));
}

__device__ __forceinline__ void mma16(float* c, const uint32_t* a, const uint32_t* b) {
    asm volatile(
        "mma.sync.aligned.m16n8k16.row.col.f32.f16.f16.f32 "
        "{%0,%1,%2,%3}, {%4,%5,%6,%7}, {%8,%9}, {%0,%1,%2,%3};"
        : "+f"(c[0]), "+f"(c[1]), "+f"(c[2]), "+f"(c[3])
        : "r"(a[0]), "r"(a[1]), "r"(a[2]), "r"(a[3]),
          "r"(b[0]), "r"(b[1]));
}

// ---------------------------------------------------------------------------
// fp16 NT GEMM (ldmatrix fragments, ks-level double buffering).
// C[M,N] = scale * A[M,K] @ B[N,K]^T (+bias)
// CTA 128(M) x 256(N), BK=64 halves, 3-stage cp.async, 8 warps of 64x64.
// SMEM row = 128B (64 halves); 16B chunk c of row r stored at c ^ (r&7).
// ---------------------------------------------------------------------------
#define BM 128
#define BN 256
#define BK 64
#define A_BYTES     16384u                 // 128 * 128B
#define STAGE_BYTES 49152u                 // (128+256) * 128B
#define GEMM_SMEM   (3 * 49152)            // 147456

template <bool CAUSAL, bool HASBIAS, bool HALFOUT>
__global__ void __launch_bounds__(256, 1)
tc_nt_kernel(const __half* __restrict__ A, const __half* __restrict__ B,
             void* __restrict__ Cv, const float* __restrict__ bias,
             int M, int N, int K, int lda, int ldb, int ldc, float scale,
             size_t sA, size_t sB, size_t sC, int kClamp)
{
    extern __shared__ __align__(16) char smc[];
    A += (size_t)blockIdx.z * sA;
    B += (size_t)blockIdx.z * sB;
    const int m0 = blockIdx.x * BM;
    const int n0 = blockIdx.y * BN;
    if (CAUSAL && n0 > m0 + (BM - 1)) return;

    const int tid  = threadIdx.x;
    const int lane = tid & 31;
    const int wid  = tid >> 5;
    const int wm   = (wid & 1) * 64;
    const int wn   = (wid >> 1) * 64;
    const uint32_t su = s2u(smc);

    // ---- loaders
    const int lrow  = tid >> 1;
    const int cbase = (tid & 1) * 4;
    const __half* Ag  = A + (size_t)(m0 + lrow) * lda + cbase * 8;
    const __half* Bg0 = B + (size_t)(n0 + lrow) * ldb + cbase * 8;
    const __half* Bg1 = Bg0 + (size_t)128 * ldb;
    uint32_t adst[4], bdst[4];
#pragma unroll
    for (int i = 0; i < 4; i++) {
        const int c = cbase + i;
        adst[i] = (uint32_t)(lrow * 128 + ((c ^ (lrow & 7)) << 4));
        bdst[i] = adst[i] + A_BYTES;
    }

    const int kEnd = kClamp ? (m0 + BM < K ? m0 + BM : K) : K;
    const int nk = kEnd / BK;

#pragma unroll
    for (int st = 0; st < 2; st++) {
        const uint32_t sb = su + (uint32_t)st * STAGE_BYTES;
        const int kh = st * BK;
#pragma unroll
        for (int i = 0; i < 4; i++) {
            cpasync16(sb + adst[i],               Ag  + kh + i * 8);
            cpasync16(sb + bdst[i],               Bg0 + kh + i * 8);
            cpasync16(sb + bdst[i] + 128u * 128u, Bg1 + kh + i * 8);
        }
        CP_COMMIT();
    }

    float acc[4][8][4];
#pragma unroll
    for (int mt = 0; mt < 4; mt++)
#pragma unroll
        for (int nt = 0; nt < 8; nt++)
#pragma unroll
            for (int j = 0; j < 4; j++) acc[mt][nt][j] = 0.f;

    // ---- per-lane ldmatrix addressing
    const int arow = wm + (lane & 7) + (((lane >> 3) & 1) << 3);
    const uint32_t aRowOff = (uint32_t)arow * 128u;
    const int aS  = arow & 7;
    const int aKh = lane >> 4;
    const int brow = wn + (lane & 7) + ((lane >> 4) << 3);
    const uint32_t bRowOff = (uint32_t)brow * 128u + A_BYTES;
    const int bS  = brow & 7;
    const int bKh = (lane >> 3) & 1;

    uint32_t af[2][4][4], bf[2][8][2];

    for (int c = 0; c < nk; c++) {
        CP_WAIT1();
        __syncthreads();

        const uint32_t stg = su + (uint32_t)(c % 3) * STAGE_BYTES;

        // fragment load for ks=0 FIRST (longest dependency)
        {
            const uint32_t baseA = stg + aRowOff + (uint32_t)((aKh ^ aS) << 4);
#pragma unroll
            for (int mt = 0; mt < 4; mt++)
                ldsm4(af[0][mt], baseA + (uint32_t)mt * 2048u);
            const uint32_t baseB = stg + bRowOff + (uint32_t)((bKh ^ bS) << 4);
#pragma unroll
            for (int j = 0; j < 4; j++) {
                uint32_t r[4];
                ldsm4(r, baseB + (uint32_t)j * 2048u);
                bf[0][j * 2][0]     = r[0]; bf[0][j * 2][1]     = r[1];
                bf[0][j * 2 + 1][0] = r[2]; bf[0][j * 2 + 1][1] = r[3];
            }
        }

        const int p = c + 2;
        if (p < nk) {
            const uint32_t sb = su + (uint32_t)(p % 3) * STAGE_BYTES;
            const int kh = p * BK;
#pragma unroll
            for (int i = 0; i < 4; i++) {
                cpasync16(sb + adst[i],               Ag  + kh + i * 8);
                cpasync16(sb + bdst[i],               Bg0 + kh + i * 8);
                cpasync16(sb + bdst[i] + 128u * 128u, Bg1 + kh + i * 8);
            }
        }
        CP_COMMIT();

#pragma unroll
        for (int ks = 0; ks < 4; ks++) {
            const int cur = ks & 1, nxt = cur ^ 1;
            if (ks < 3) {   // prefetch ks+1 fragments before current MMAs
                const uint32_t coA = (uint32_t)((((ks + 1) * 2 + aKh) ^ aS) << 4);
                const uint32_t baseA = stg + aRowOff + coA;
#pragma unroll
                for (int mt = 0; mt < 4; mt++)
                    ldsm4(af[nxt][mt], baseA + (uint32_t)mt * 2048u);
                const uint32_t coB = (uint32_t)((((ks + 1) * 2 + bKh) ^ bS) << 4);
                const uint32_t baseB = stg + bRowOff + coB;
#pragma unroll
                for (int j = 0; j < 4; j++) {
                    uint32_t r[4];
                    ldsm4(r, baseB + (uint32_t)j * 2048u);
                    bf[nxt][j * 2][0]     = r[0]; bf[nxt][j * 2][1]     = r[1];
                    bf[nxt][j * 2 + 1][0] = r[2]; bf[nxt][j * 2 + 1][1] = r[3];
                }
            }
#pragma unroll
            for (int mt = 0; mt < 4; mt++)
#pragma unroll
                for (int nt = 0; nt < 8; nt++)
                    mma16(acc[mt][nt], af[cur][mt], bf[cur][nt]);
        }
    }

    // ---- epilogue
    const int lg = lane >> 2;
    if (HALFOUT) {
        __half* Ch = (__half*)Cv + (size_t)blockIdx.z * sC;
#pragma unroll
        for (int mt = 0; mt < 4; mt++) {
            const int r0 = m0 + wm + mt * 16 + lg;
#pragma unroll
            for (int nt = 0; nt < 8; nt++) {
                const int col = n0 + wn + nt * 8 + (lane & 3) * 2;
                __half2 v0 = __floats2half2_rn(acc[mt][nt][0] * scale,
                                               acc[mt][nt][1] * scale);
                __half2 v1 = __floats2half2_rn(acc[mt][nt][2] * scale,
                                               acc[mt][nt][3] * scale);
                *reinterpret_cast<__half2*>(Ch + (size_t)r0 * ldc + col)       = v0;
                *reinterpret_cast<__half2*>(Ch + (size_t)(r0 + 8) * ldc + col) = v1;
            }
        }
    } else {
        float* Cf = (float*)Cv + (size_t)blockIdx.z * sC;
#pragma unroll
        for (int mt = 0; mt < 4; mt++) {
            const int r0 = m0 + wm + mt * 16 + lg;
#pragma unroll
            for (int nt = 0; nt < 8; nt++) {
                const int col = n0 + wn + nt * 8 + (lane & 3) * 2;
                float bx = 0.f, by = 0.f;
                if (HASBIAS) {
                    float2 bv = *reinterpret_cast<const float2*>(bias + col);
                    bx = bv.x; by = bv.y;
                }
                float2 v0 = make_float2(acc[mt][nt][0] * scale + bx,
                                        acc[mt][nt][1] * scale + by);
                float2 v1 = make_float2(acc[mt][nt][2] * scale + bx,
                                        acc[mt][nt][3] * scale + by);
                *reinterpret_cast<float2*>(Cf + (size_t)r0 * ldc + col)       = v0;
                *reinterpret_cast<float2*>(Cf + (size_t)(r0 + 8) * ldc + col) = v1;
            }
        }
    }
}

// ---------------------------------------------------------------------------
// Pack: fp32 -> fp16
// ---------------------------------------------------------------------------
__global__ void pack_kernel(const float* __restrict__ in, __half* __restrict__ out,
                            size_t n4)
{
    size_t i = (size_t)blockIdx.x * blockDim.x + threadIdx.x;
    if (i >= n4) return;
    const size_t el = i * 4;
    const float4 q = *reinterpret_cast<const float4*>(in + el);
    *reinterpret_cast<__half2*>(out + el)     = __floats2half2_rn(q.x, q.y);
    *reinterpret_cast<__half2*>(out + el + 2) = __floats2half2_rn(q.z, q.w);
}

// ---------------------------------------------------------------------------
// Masked causal softmax: fp32 scores in, fp16 attn out.
// ---------------------------------------------------------------------------
__global__ void softmax_kernel(float* __restrict__ scores,
                               __half* __restrict__ attn,
                               const int* __restrict__ mask)
{
    const int t = blockIdx.x;
    const int b = blockIdx.y;
    float* row = scores + ((size_t)b * TT + t) * TT;
    __half* arow = attn + ((size_t)b * TT + t) * TT;
    const int* mrow = mask + b * TT;
    const int tid = threadIdx.x;

    __shared__ float red[256];

    float mx = -INFINITY;
    for (int s = tid; s <= t; s += 256)
        if (mrow[s]) mx = fmaxf(mx, row[s]);
    red[tid] = mx;
    __syncthreads();
    for (int w = 128; w > 0; w >>= 1) {
        if (tid < w) red[tid] = fmaxf(red[tid], red[tid + w]);
        __syncthreads();
    }
    mx = red[0];
    __syncthreads();

    float sum = 0.f;
    for (int s = tid; s < TT; s += 256) {
        float val = 0.f;
        if (s <= t && mrow[s]) {
            val = expf(row[s] - mx);
            sum += val;
        }
        row[s] = val;
    }
    red[tid] = sum;
    __syncthreads();
    for (int w = 128; w > 0; w >>= 1) {
        if (tid < w) red[tid] += red[tid + w];
        __syncthreads();
    }
    sum = red[0];
    __syncthreads();

    const float inv = (sum > 0.f) ? 1.f / sum : 0.f;
    for (int s = tid; s < TT; s += 256)
        arow[s] = __float2half(row[s] * inv);
}

// ---------------------------------------------------------------------------
// Launch
// ---------------------------------------------------------------------------
static inline int cdiv_sz(size_t a, int b) { return (int)((a + b - 1) / b); }

extern "C" void kernel_launch(void* const* d_in, const int* in_sizes, int n_in,
                              void* d_out, int out_size)
{
    const float* h    = (const float*)d_in[0];
    const float* e    = (const float*)d_in[1];
    const int*   mask = (const int*)  d_in[2];
    const float* Wq   = (const float*)d_in[3];
    const float* Wk   = (const float*)d_in[4];
    const float* Wv   = (const float*)d_in[5];
    const float* Wout = (const float*)d_in[6];
    const float* bout = (const float*)d_in[7];
    float* out = (float*)d_out;

    __half *hp, *ep, *wqp, *wkp, *wvp, *wop, *q, *k, *vT, *ctx, *attn;
    float *sc;
    cudaGetSymbolAddress((void**)&hp,   g_hp);
    cudaGetSymbolAddress((void**)&ep,   g_ep);
    cudaGetSymbolAddress((void**)&wqp,  g_wqp);
    cudaGetSymbolAddress((void**)&wkp,  g_wkp);
    cudaGetSymbolAddress((void**)&wvp,  g_wvp);
    cudaGetSymbolAddress((void**)&wop,  g_wop);
    cudaGetSymbolAddress((void**)&q,    g_q);
    cudaGetSymbolAddress((void**)&k,    g_k);
    cudaGetSymbolAddress((void**)&vT,   g_vT);
    cudaGetSymbolAddress((void**)&ctx,  g_ctx);
    cudaGetSymbolAddress((void**)&attn, g_attn);
    cudaGetSymbolAddress((void**)&sc,   g_scores);

    cudaFuncSetAttribute(tc_nt_kernel<false, false, true>,
                         cudaFuncAttributeMaxDynamicSharedMemorySize, GEMM_SMEM);
    cudaFuncSetAttribute(tc_nt_kernel<true, false, false>,
                         cudaFuncAttributeMaxDynamicSharedMemorySize, GEMM_SMEM);
    cudaFuncSetAttribute(tc_nt_kernel<false, true, false>,
                         cudaFuncAttributeMaxDynamicSharedMemorySize, GEMM_SMEM);

    const float att_scale = 1.0f / 32.0f;   // KV^-0.5
    const int PT = 256;

    // 0) pack inputs + weights
    pack_kernel<<<cdiv_sz((size_t)MTOT*HID/4, PT), PT>>>(h,    hp,  (size_t)MTOT*HID/4);
    pack_kernel<<<cdiv_sz((size_t)MTOT*HID/4, PT), PT>>>(e,    ep,  (size_t)MTOT*HID/4);
    pack_kernel<<<cdiv_sz((size_t)KVD*HID/4,  PT), PT>>>(Wq,   wqp, (size_t)KVD*HID/4);
    pack_kernel<<<cdiv_sz((size_t)KVD*HID/4,  PT), PT>>>(Wk,   wkp, (size_t)KVD*HID/4);
    pack_kernel<<<cdiv_sz((size_t)KVD*HID/4,  PT), PT>>>(Wv,   wvp, (size_t)KVD*HID/4);
    pack_kernel<<<cdiv_sz((size_t)VOC*KVD/4,  PT), PT>>>(Wout, wop, (size_t)VOC*KVD/4);

    // 1) q = h @ Wq^T, k = e @ Wk^T
    {
        dim3 grid(MTOT / BM, KVD / BN, 1);
        tc_nt_kernel<false, false, true><<<grid, 256, GEMM_SMEM>>>(
            hp, wqp, q, nullptr, MTOT, KVD, HID, HID, HID, KVD, 1.f, 0, 0, 0, 0);
        tc_nt_kernel<false, false, true><<<grid, 256, GEMM_SMEM>>>(
            ep, wkp, k, nullptr, MTOT, KVD, HID, HID, HID, KVD, 1.f, 0, 0, 0, 0);
    }

    // 1b) vT = Wv @ e^T : [KVD, MTOT]
    {
        dim3 grid(KVD / BM, MTOT / BN, 1);
        tc_nt_kernel<false, false, true><<<grid, 256, GEMM_SMEM>>>(
            wvp, ep, vT, nullptr, KVD, MTOT, HID, HID, HID, MTOT, 1.f, 0, 0, 0, 0);
    }

    // 2) scores = scale * q @ k^T (causal block-skip), fp32 out, per batch
    {
        dim3 grid(TT / BM, TT / BN, BBATCH);
        tc_nt_kernel<true, false, false><<<grid, 256, GEMM_SMEM>>>(
            q, k, sc, nullptr, TT, TT, KVD, KVD, KVD, TT, att_scale,
            (size_t)TT * KVD, (size_t)TT * KVD, (size_t)TT * TT, 0);
    }

    // 3) softmax -> fp16 attn
    {
        dim3 grid(TT, BBATCH);
        softmax_kernel<<<grid, 256>>>(sc, attn, mask);
    }

    // 4) ctx = attn @ V = NT(attn, vT), K clamped by causality
    {
        dim3 grid(TT / BM, KVD / BN, BBATCH);
        tc_nt_kernel<false, false, true><<<grid, 256, GEMM_SMEM>>>(
            attn, vT, ctx, nullptr, TT, KVD, TT, TT, MTOT, KVD, 1.f,
            (size_t)TT * TT, (size_t)TT, (size_t)TT * KVD, 1);
    }

    // 5) out = ctx @ Wout^T + bout
    {
        dim3 grid(MTOT / BM, VOC / BN, 1);
        tc_nt_kernel<false, true, false><<<grid, 256, GEMM_SMEM>>>(
            ctx, wop, out, bout, MTOT, VOC, KVD, KVD, KVD, VOC, 1.f, 0, 0, 0, 0);
    }
}

// round 9
// speedup vs baseline: 1.0178x; 1.0178x over previous
#include <cuda_runtime.h>
#include <cuda_fp16.h>
#include <cstddef>
#include <cstdint>
#include <math.h>

// ---------------------------------------------------------------------------
// Problem dims
// ---------------------------------------------------------------------------
#define BBATCH 2
#define TT   2048
#define HID  2048
#define KVD  1024
#define VOC  32000
#define MTOT (BBATCH * TT)   // 4096

// ---------------------------------------------------------------------------
// Scratch. fp16 buffers hold k-permuted data: within each 16-group, order is
// [0,1,8,9, 2,3,10,11, 4,5,12,13, 6,7,14,15]  (quad [k,k+1,k+8,k+9] adjacent)
// ---------------------------------------------------------------------------
__device__ __align__(256) __half g_hp [(size_t)MTOT * HID];
__device__ __align__(256) __half g_ep [(size_t)MTOT * HID];
__device__ __align__(256) __half g_wqp[(size_t)KVD * HID];
__device__ __align__(256) __half g_wkp[(size_t)KVD * HID];
__device__ __align__(256) __half g_wvp[(size_t)KVD * HID];
__device__ __align__(256) __half g_wop[(size_t)VOC * KVD];
__device__ __align__(256) __half g_q  [(size_t)MTOT * KVD];
__device__ __align__(256) __half g_k  [(size_t)MTOT * KVD];
__device__ __align__(256) __half g_vT [(size_t)KVD * MTOT];     // [KVD, B*T]
__device__ __align__(256) __half g_ctx[(size_t)MTOT * KVD];
__device__ __align__(256) __half g_attn[(size_t)MTOT * TT];
__device__ __align__(256) float  g_scores[(size_t)BBATCH * TT * TT];

// ---------------------------------------------------------------------------
// Helpers
// ---------------------------------------------------------------------------
__device__ __forceinline__ uint32_t s2u(const void* p) {
    uint32_t a;
    asm("{ .reg .u64 t; cvta.to.shared.u64 t, %1; cvt.u32.u64 %0, t; }"
        : "=r"(a) : "l"(p));
    return a;
}

__device__ __forceinline__ void cpasync16(uint32_t dst, const void* src) {
    asm volatile("cp.async.cg.shared.global [%0], [%1], 16;"
                 :: "r"(dst), "l"(src));
}
#define CP_COMMIT() asm volatile("cp.async.commit_group;" ::: "memory")
#define CP_WAIT1()  asm volatile("cp.async.wait_group 1;"  ::: "memory")

__device__ __forceinline__ void mma16(float* c, const uint32_t* a, const uint32_t* b) {
    asm volatile(
        "mma.sync.aligned.m16n8k16.row.col.f32.f16.f16.f32 "
        "{%0,%1,%2,%3}, {%4,%5,%6,%7}, {%8,%9}, {%0,%1,%2,%3};"
        : "+f"(c[0]), "+f"(c[1]), "+f"(c[2]), "+f"(c[3])
        : "r"(a[0]), "r"(a[1]), "r"(a[2]), "r"(a[3]),
          "r"(b[0]), "r"(b[1]));
}

// permuted slot for even local index e (0..15)
__device__ __forceinline__ int slot_even(int e) {
    return (((e >> 1) & 3) << 2) + (((e >> 3) & 1) << 1);
}

// ---------------------------------------------------------------------------
// fp16 NT GEMM on pre-permuted operands (R6 mainloop, occupancy-2 shape).
// C[M,N] = scale * A[M,K] @ B[N,K]^T (+ bias)
// CTA 128(M) x 128(N), BK=32 halves, 3-stage cp.async, 8 warps of 64x32.
// SMEM: row = 64B (32 halves); 32B-half of row swizzled by ((row>>1)&1).
// ---------------------------------------------------------------------------
#define BM 128
#define BN 128
#define STAGE_BYTES 16384u                 // (128+128) * 64B
#define B_OFF_BYTES 8192u                  // A = 128*64
#define GEMM_SMEM   (3 * 16384)            // 49152

template <bool CAUSAL, bool HASBIAS, bool HALFOUT>
__global__ void __launch_bounds__(256, 2)
tc_nt_kernel(const __half* __restrict__ A, const __half* __restrict__ B,
             void* __restrict__ Cv, const float* __restrict__ bias,
             int M, int N, int K, int lda, int ldb, int ldc, float scale,
             size_t sA, size_t sB, size_t sC, int kClamp)
{
    extern __shared__ __align__(16) char smc[];
    A += (size_t)blockIdx.z * sA;
    B += (size_t)blockIdx.z * sB;
    const int m0 = blockIdx.x * BM;
    const int n0 = blockIdx.y * BN;
    if (CAUSAL && n0 > m0 + (BM - 1)) return;

    const int tid  = threadIdx.x;
    const int lane = tid & 31;
    const int wid  = tid >> 5;
    const int wm   = (wid & 1) * 64;        // 2 m-halves
    const int wn   = (wid >> 1) * 32;       // 4 n-quarters
    const uint32_t su = s2u(smc);

    // ---- loaders: thread t -> row t>>1, 16B chunks (t&1)*2 .. +1
    const int lrow  = tid >> 1;
    const int cpair = (tid & 1) * 2;
    const uint32_t sw2 = (((uint32_t)lrow >> 1) & 1u) << 1;   // chunk-index XOR
    uint32_t dst0 = (uint32_t)lrow * 64u + (((uint32_t)cpair ^ sw2) << 4);
    uint32_t dst1 = (uint32_t)lrow * 64u + ((((uint32_t)cpair + 1u) ^ sw2) << 4);
    const __half* Ag = A + (size_t)(m0 + lrow) * lda + cpair * 8;
    const __half* Bg = B + (size_t)(n0 + lrow) * ldb + cpair * 8;

    const int kEnd = kClamp ? (m0 + BM < K ? m0 + BM : K) : K;
    const int nk = kEnd / 32;

#pragma unroll
    for (int st = 0; st < 2; st++) {
        const uint32_t sb = su + (uint32_t)st * STAGE_BYTES;
        const int kh = st * 32;
        cpasync16(sb + dst0,               Ag + kh);
        cpasync16(sb + dst1,               Ag + kh + 8);
        cpasync16(sb + B_OFF_BYTES + dst0, Bg + kh);
        cpasync16(sb + B_OFF_BYTES + dst1, Bg + kh + 8);
        CP_COMMIT();
    }

    float acc[4][4][4];
#pragma unroll
    for (int mt = 0; mt < 4; mt++)
#pragma unroll
        for (int nt = 0; nt < 4; nt++)
#pragma unroll
            for (int j = 0; j < 4; j++) acc[mt][nt][j] = 0.f;

    const int lg = lane >> 2;
    const int lq = (lane & 3) * 4;          // quad offset in halves

    for (int c = 0; c < nk; c++) {
        CP_WAIT1();
        __syncthreads();

        const int p = c + 2;
        if (p < nk) {
            const uint32_t sb = su + (uint32_t)(p % 3) * STAGE_BYTES;
            const int kh = p * 32;
            cpasync16(sb + dst0,               Ag + kh);
            cpasync16(sb + dst1,               Ag + kh + 8);
            cpasync16(sb + B_OFF_BYTES + dst0, Bg + kh);
            cpasync16(sb + B_OFF_BYTES + dst1, Bg + kh + 8);
        }
        CP_COMMIT();

        const __half* sA_ = (const __half*)(smc + (c % 3) * STAGE_BYTES);
        const __half* sB_ = sA_ + 4096;     // +8192 bytes

#pragma unroll
        for (int ks = 0; ks < 2; ks++) {
            const int kh = ks * 16 + lq;
            uint32_t af[4][4], bf[4][2];
#pragma unroll
            for (int nt = 0; nt < 4; nt++) {
                const int n = wn + nt * 8 + lg;
                const uint2 bv = *reinterpret_cast<const uint2*>(
                    sB_ + n * 32 + (kh ^ (((n >> 1) & 1) << 4)));
                bf[nt][0] = bv.x; bf[nt][1] = bv.y;
            }
#pragma unroll
            for (int mt = 0; mt < 4; mt++) {
                const int m = wm + mt * 16 + lg;
                const int sw = ((m >> 1) & 1) << 4;
                const uint2 lm  = *reinterpret_cast<const uint2*>(
                    sA_ + m * 32 + (kh ^ sw));
                const uint2 lm8 = *reinterpret_cast<const uint2*>(
                    sA_ + (m + 8) * 32 + (kh ^ sw));
                af[mt][0] = lm.x;  af[mt][1] = lm8.x;
                af[mt][2] = lm.y;  af[mt][3] = lm8.y;
            }
#pragma unroll
            for (int mt = 0; mt < 4; mt++)
#pragma unroll
                for (int nt = 0; nt < 4; nt++)
                    mma16(acc[mt][nt], af[mt], bf[nt]);
        }
    }

    // ---- epilogue
    if (HALFOUT) {
        __half* Ch = (__half*)Cv + (size_t)blockIdx.z * sC;
#pragma unroll
        for (int mt = 0; mt < 4; mt++) {
            const int r0 = m0 + wm + mt * 16 + lg;
#pragma unroll
            for (int nt = 0; nt < 4; nt++) {
                const int col = n0 + wn + nt * 8 + (lane & 3) * 2;
                const int pc = (col & ~15) + slot_even(col & 15);
                __half2 v0 = __floats2half2_rn(acc[mt][nt][0] * scale,
                                               acc[mt][nt][1] * scale);
                __half2 v1 = __floats2half2_rn(acc[mt][nt][2] * scale,
                                               acc[mt][nt][3] * scale);
                *reinterpret_cast<__half2*>(Ch + (size_t)r0 * ldc + pc)       = v0;
                *reinterpret_cast<__half2*>(Ch + (size_t)(r0 + 8) * ldc + pc) = v1;
            }
        }
    } else {
        float* Cf = (float*)Cv + (size_t)blockIdx.z * sC;
#pragma unroll
        for (int mt = 0; mt < 4; mt++) {
            const int r0 = m0 + wm + mt * 16 + lg;
#pragma unroll
            for (int nt = 0; nt < 4; nt++) {
                const int col = n0 + wn + nt * 8 + (lane & 3) * 2;
                float bx = 0.f, by = 0.f;
                if (HASBIAS) {
                    float2 bv = *reinterpret_cast<const float2*>(bias + col);
                    bx = bv.x; by = bv.y;
                }
                float2 v0 = make_float2(acc[mt][nt][0] * scale + bx,
                                        acc[mt][nt][1] * scale + by);
                float2 v1 = make_float2(acc[mt][nt][2] * scale + bx,
                                        acc[mt][nt][3] * scale + by);
                *reinterpret_cast<float2*>(Cf + (size_t)r0 * ldc + col)       = v0;
                *reinterpret_cast<float2*>(Cf + (size_t)(r0 + 8) * ldc + col) = v1;
            }
        }
    }
}

// ---------------------------------------------------------------------------
// Pack: fp32 -> fp16 with k-permutation (float4 per thread).
// ---------------------------------------------------------------------------
__global__ void pack_kernel(const float* __restrict__ in, __half* __restrict__ out,
                            size_t n4, int ld)
{
    size_t i = (size_t)blockIdx.x * blockDim.x + threadIdx.x;
    if (i >= n4) return;
    const size_t el = i * 4;
    const int c = (int)(el % ld);
    const size_t r = el / ld;
    const float4 q = *reinterpret_cast<const float4*>(in + el);
    __half* ob = out + r * (size_t)ld + (c & ~15);
    const int e = c & 15;
    *reinterpret_cast<__half2*>(ob + slot_even(e))     = __floats2half2_rn(q.x, q.y);
    *reinterpret_cast<__half2*>(ob + slot_even(e + 2)) = __floats2half2_rn(q.z, q.w);
}

// ---------------------------------------------------------------------------
// Masked causal softmax: reads fp32 scores, writes fp16 permuted attn.
// ---------------------------------------------------------------------------
__global__ void softmax_kernel(float* __restrict__ scores,
                               __half* __restrict__ attn,
                               const int* __restrict__ mask)
{
    const int t = blockIdx.x;
    const int b = blockIdx.y;
    float* row = scores + ((size_t)b * TT + t) * TT;
    __half* arow = attn + ((size_t)b * TT + t) * TT;
    const int* mrow = mask + b * TT;
    const int tid = threadIdx.x;

    __shared__ float red[256];

    float mx = -INFINITY;
    for (int s = tid; s <= t; s += 256)
        if (mrow[s]) mx = fmaxf(mx, row[s]);
    red[tid] = mx;
    __syncthreads();
    for (int w = 128; w > 0; w >>= 1) {
        if (tid < w) red[tid] = fmaxf(red[tid], red[tid + w]);
        __syncthreads();
    }
    mx = red[0];
    __syncthreads();

    float sum = 0.f;
    for (int s = tid; s < TT; s += 256) {
        float val = 0.f;
        if (s <= t && mrow[s]) {
            val = expf(row[s] - mx);
            sum += val;
        }
        row[s] = val;
    }
    red[tid] = sum;
    __syncthreads();
    for (int w = 128; w > 0; w >>= 1) {
        if (tid < w) red[tid] += red[tid + w];
        __syncthreads();
    }
    sum = red[0];
    __syncthreads();

    const float inv = (sum > 0.f) ? 1.f / sum : 0.f;
    for (int s = tid; s < TT; s += 256) {
        const int e = s & 15;
        const int ps = (s & ~15) + (e & 1) + (((e >> 1) & 3) << 2) + (((e >> 3) & 1) << 1);
        arow[ps] = __float2half(row[s] * inv);
    }
}

// ---------------------------------------------------------------------------
// Launch
// ---------------------------------------------------------------------------
static inline int cdiv_sz(size_t a, int b) { return (int)((a + b - 1) / b); }

extern "C" void kernel_launch(void* const* d_in, const int* in_sizes, int n_in,
                              void* d_out, int out_size)
{
    const float* h    = (const float*)d_in[0];
    const float* e    = (const float*)d_in[1];
    const int*   mask = (const int*)  d_in[2];
    const float* Wq   = (const float*)d_in[3];
    const float* Wk   = (const float*)d_in[4];
    const float* Wv   = (const float*)d_in[5];
    const float* Wout = (const float*)d_in[6];
    const float* bout = (const float*)d_in[7];
    float* out = (float*)d_out;

    __half *hp, *ep, *wqp, *wkp, *wvp, *wop, *q, *k, *vT, *ctx, *attn;
    float *sc;
    cudaGetSymbolAddress((void**)&hp,   g_hp);
    cudaGetSymbolAddress((void**)&ep,   g_ep);
    cudaGetSymbolAddress((void**)&wqp,  g_wqp);
    cudaGetSymbolAddress((void**)&wkp,  g_wkp);
    cudaGetSymbolAddress((void**)&wvp,  g_wvp);
    cudaGetSymbolAddress((void**)&wop,  g_wop);
    cudaGetSymbolAddress((void**)&q,    g_q);
    cudaGetSymbolAddress((void**)&k,    g_k);
    cudaGetSymbolAddress((void**)&vT,   g_vT);
    cudaGetSymbolAddress((void**)&ctx,  g_ctx);
    cudaGetSymbolAddress((void**)&attn, g_attn);
    cudaGetSymbolAddress((void**)&sc,   g_scores);

    cudaFuncSetAttribute(tc_nt_kernel<false, false, true>,
                         cudaFuncAttributeMaxDynamicSharedMemorySize, GEMM_SMEM);
    cudaFuncSetAttribute(tc_nt_kernel<true, false, false>,
                         cudaFuncAttributeMaxDynamicSharedMemorySize, GEMM_SMEM);
    cudaFuncSetAttribute(tc_nt_kernel<false, true, false>,
                         cudaFuncAttributeMaxDynamicSharedMemorySize, GEMM_SMEM);

    const float att_scale = 1.0f / 32.0f;   // KV^-0.5
    const int PT = 256;

    // 0) pack inputs + weights (fp16 + permute)
    pack_kernel<<<cdiv_sz((size_t)MTOT*HID/4, PT), PT>>>(h,    hp,  (size_t)MTOT*HID/4, HID);
    pack_kernel<<<cdiv_sz((size_t)MTOT*HID/4, PT), PT>>>(e,    ep,  (size_t)MTOT*HID/4, HID);
    pack_kernel<<<cdiv_sz((size_t)KVD*HID/4,  PT), PT>>>(Wq,   wqp, (size_t)KVD*HID/4,  HID);
    pack_kernel<<<cdiv_sz((size_t)KVD*HID/4,  PT), PT>>>(Wk,   wkp, (size_t)KVD*HID/4,  HID);
    pack_kernel<<<cdiv_sz((size_t)KVD*HID/4,  PT), PT>>>(Wv,   wvp, (size_t)KVD*HID/4,  HID);
    pack_kernel<<<cdiv_sz((size_t)VOC*KVD/4,  PT), PT>>>(Wout, wop, (size_t)VOC*KVD/4,  KVD);

    // 1) q = h @ Wq^T, k = e @ Wk^T  (fp16-permuted outputs)
    {
        dim3 grid(MTOT / BM, KVD / BN, 1);
        tc_nt_kernel<false, false, true><<<grid, 256, GEMM_SMEM>>>(
            hp, wqp, q, nullptr, MTOT, KVD, HID, HID, HID, KVD, 1.f, 0, 0, 0, 0);
        tc_nt_kernel<false, false, true><<<grid, 256, GEMM_SMEM>>>(
            ep, wkp, k, nullptr, MTOT, KVD, HID, HID, HID, KVD, 1.f, 0, 0, 0, 0);
    }

    // 1b) vT = Wv @ e^T : [KVD, MTOT]
    {
        dim3 grid(KVD / BM, MTOT / BN, 1);
        tc_nt_kernel<false, false, true><<<grid, 256, GEMM_SMEM>>>(
            wvp, ep, vT, nullptr, KVD, MTOT, HID, HID, HID, MTOT, 1.f, 0, 0, 0, 0);
    }

    // 2) scores = scale * q @ k^T (causal block-skip), fp32 out, per batch
    {
        dim3 grid(TT / BM, TT / BN, BBATCH);
        tc_nt_kernel<true, false, false><<<grid, 256, GEMM_SMEM>>>(
            q, k, sc, nullptr, TT, TT, KVD, KVD, KVD, TT, att_scale,
            (size_t)TT * KVD, (size_t)TT * KVD, (size_t)TT * TT, 0);
    }

    // 3) softmax -> fp16 permuted attn
    {
        dim3 grid(TT, BBATCH);
        softmax_kernel<<<grid, 256>>>(sc, attn, mask);
    }

    // 4) ctx = attn @ V = NT(attn, vT), K clamped by causality
    {
        dim3 grid(TT / BM, KVD / BN, BBATCH);
        tc_nt_kernel<false, false, true><<<grid, 256, GEMM_SMEM>>>(
            attn, vT, ctx, nullptr, TT, KVD, TT, TT, MTOT, KVD, 1.f,
            (size_t)TT * TT, (size_t)TT, (size_t)TT * KVD, 1);
    }

    // 5) out = ctx @ Wout^T + bout  (m-fast grid: ctx stays L2-resident)
    {
        dim3 grid(MTOT / BM, VOC / BN, 1);
        tc_nt_kernel<false, true, false><<<grid, 256, GEMM_SMEM>>>(
            ctx, wop, out, bout, MTOT, VOC, KVD, KVD, KVD, VOC, 1.f, 0, 0, 0, 0);
    }
}

// round 10
// speedup vs baseline: 1.0187x; 1.0008x over previous
#include <cuda_runtime.h>
#include <cuda_fp16.h>
#include <cstddef>
#include <cstdint>
#include <math.h>

// ---------------------------------------------------------------------------
// Problem dims
// ---------------------------------------------------------------------------
#define BBATCH 2
#define TT   2048
#define HID  2048
#define KVD  1024
#define VOC  32000
#define MTOT (BBATCH * TT)   // 4096

// ---------------------------------------------------------------------------
// Scratch. fp16 buffers hold k-permuted data: within each 16-group, order is
// [0,1,8,9, 2,3,10,11, 4,5,12,13, 6,7,14,15]  (quad [k,k+1,k+8,k+9] adjacent)
// ---------------------------------------------------------------------------
__device__ __align__(256) __half g_hp [(size_t)MTOT * HID];
__device__ __align__(256) __half g_ep [(size_t)MTOT * HID];
__device__ __align__(256) __half g_wqp[(size_t)KVD * HID];
__device__ __align__(256) __half g_wkp[(size_t)KVD * HID];
__device__ __align__(256) __half g_wvp[(size_t)KVD * HID];
__device__ __align__(256) __half g_wop[(size_t)VOC * KVD];
__device__ __align__(256) __half g_q  [(size_t)MTOT * KVD];
__device__ __align__(256) __half g_k  [(size_t)MTOT * KVD];
__device__ __align__(256) __half g_vT [(size_t)KVD * MTOT];     // [KVD, B*T]
__device__ __align__(256) __half g_ctx[(size_t)MTOT * KVD];
__device__ __align__(256) __half g_attn[(size_t)MTOT * TT];
__device__ __align__(256) float  g_scores[(size_t)BBATCH * TT * TT];

// ---------------------------------------------------------------------------
// Helpers
// ---------------------------------------------------------------------------
__device__ __forceinline__ uint32_t s2u(const void* p) {
    uint32_t a;
    asm("{ .reg .u64 t; cvta.to.shared.u64 t, %1; cvt.u32.u64 %0, t; }"
        : "=r"(a) : "l"(p));
    return a;
}

__device__ __forceinline__ void cpasync16(uint32_t dst, const void* src) {
    asm volatile("cp.async.cg.shared.global [%0], [%1], 16;"
                 :: "r"(dst), "l"(src));
}
#define CP_COMMIT() asm volatile("cp.async.commit_group;" ::: "memory")
#define CP_WAIT1()  asm volatile("cp.async.wait_group 1;"  ::: "memory")

__device__ __forceinline__ void mma16(float* c, const uint32_t* a, const uint32_t* b) {
    asm volatile(
        "mma.sync.aligned.m16n8k16.row.col.f32.f16.f16.f32 "
        "{%0,%1,%2,%3}, {%4,%5,%6,%7}, {%8,%9}, {%0,%1,%2,%3};"
        : "+f"(c[0]), "+f"(c[1]), "+f"(c[2]), "+f"(c[3])
        : "r"(a[0]), "r"(a[1]), "r"(a[2]), "r"(a[3]),
          "r"(b[0]), "r"(b[1]));
}

// permuted slot for even local index e (0..15)
__device__ __forceinline__ int slot_even(int e) {
    return (((e >> 1) & 3) << 2) + (((e >> 3) & 1) << 1);
}

// ---------------------------------------------------------------------------
// fp16 NT GEMM on pre-permuted operands (R6 mainloop, occupancy-2 shape).
// C[M,N] = scale * A[M,K] @ B[N,K]^T (+ bias)
// CTA 128(M) x 128(N), BK=32 halves, 3-stage cp.async, 8 warps of 64x32.
// SMEM: row = 64B (32 halves); 32B-half of row swizzled by ((row>>1)&1).
// ---------------------------------------------------------------------------
#define BM 128
#define BN 128
#define STAGE_BYTES 16384u                 // (128+128) * 64B
#define B_OFF_BYTES 8192u                  // A = 128*64
#define GEMM_SMEM   (3 * 16384)            // 49152

template <bool CAUSAL, bool HASBIAS, bool HALFOUT>
__global__ void __launch_bounds__(256, 2)
tc_nt_kernel(const __half* __restrict__ A, const __half* __restrict__ B,
             void* __restrict__ Cv, const float* __restrict__ bias,
             int M, int N, int K, int lda, int ldb, int ldc, float scale,
             size_t sA, size_t sB, size_t sC, int kClamp)
{
    extern __shared__ __align__(16) char smc[];
    A += (size_t)blockIdx.z * sA;
    B += (size_t)blockIdx.z * sB;
    const int m0 = blockIdx.x * BM;
    const int n0 = blockIdx.y * BN;
    if (CAUSAL && n0 > m0 + (BM - 1)) return;

    const int tid  = threadIdx.x;
    const int lane = tid & 31;
    const int wid  = tid >> 5;
    const int wm   = (wid & 1) * 64;        // 2 m-halves
    const int wn   = (wid >> 1) * 32;       // 4 n-quarters
    const uint32_t su = s2u(smc);

    // ---- loaders: thread t -> row t>>1, 16B chunks (t&1)*2 .. +1
    const int lrow  = tid >> 1;
    const int cpair = (tid & 1) * 2;
    const uint32_t sw2 = (((uint32_t)lrow >> 1) & 1u) << 1;   // chunk-index XOR
    uint32_t dst0 = (uint32_t)lrow * 64u + (((uint32_t)cpair ^ sw2) << 4);
    uint32_t dst1 = (uint32_t)lrow * 64u + ((((uint32_t)cpair + 1u) ^ sw2) << 4);
    const __half* Ag = A + (size_t)(m0 + lrow) * lda + cpair * 8;
    const __half* Bg = B + (size_t)(n0 + lrow) * ldb + cpair * 8;

    const int kEnd = kClamp ? (m0 + BM < K ? m0 + BM : K) : K;
    const int nk = kEnd / 32;

#pragma unroll
    for (int st = 0; st < 2; st++) {
        const uint32_t sb = su + (uint32_t)st * STAGE_BYTES;
        const int kh = st * 32;
        cpasync16(sb + dst0,               Ag + kh);
        cpasync16(sb + dst1,               Ag + kh + 8);
        cpasync16(sb + B_OFF_BYTES + dst0, Bg + kh);
        cpasync16(sb + B_OFF_BYTES + dst1, Bg + kh + 8);
        CP_COMMIT();
    }

    float acc[4][4][4];
#pragma unroll
    for (int mt = 0; mt < 4; mt++)
#pragma unroll
        for (int nt = 0; nt < 4; nt++)
#pragma unroll
            for (int j = 0; j < 4; j++) acc[mt][nt][j] = 0.f;

    const int lg = lane >> 2;
    const int lq = (lane & 3) * 4;          // quad offset in halves

    for (int c = 0; c < nk; c++) {
        CP_WAIT1();
        __syncthreads();

        const int p = c + 2;
        if (p < nk) {
            const uint32_t sb = su + (uint32_t)(p % 3) * STAGE_BYTES;
            const int kh = p * 32;
            cpasync16(sb + dst0,               Ag + kh);
            cpasync16(sb + dst1,               Ag + kh + 8);
            cpasync16(sb + B_OFF_BYTES + dst0, Bg + kh);
            cpasync16(sb + B_OFF_BYTES + dst1, Bg + kh + 8);
        }
        CP_COMMIT();

        const __half* sA_ = (const __half*)(smc + (c % 3) * STAGE_BYTES);
        const __half* sB_ = sA_ + 4096;     // +8192 bytes

#pragma unroll
        for (int ks = 0; ks < 2; ks++) {
            const int kh = ks * 16 + lq;
            uint32_t af[4][4], bf[4][2];
#pragma unroll
            for (int nt = 0; nt < 4; nt++) {
                const int n = wn + nt * 8 + lg;
                const uint2 bv = *reinterpret_cast<const uint2*>(
                    sB_ + n * 32 + (kh ^ (((n >> 1) & 1) << 4)));
                bf[nt][0] = bv.x; bf[nt][1] = bv.y;
            }
#pragma unroll
            for (int mt = 0; mt < 4; mt++) {
                const int m = wm + mt * 16 + lg;
                const int sw = ((m >> 1) & 1) << 4;
                const uint2 lm  = *reinterpret_cast<const uint2*>(
                    sA_ + m * 32 + (kh ^ sw));
                const uint2 lm8 = *reinterpret_cast<const uint2*>(
                    sA_ + (m + 8) * 32 + (kh ^ sw));
                af[mt][0] = lm.x;  af[mt][1] = lm8.x;
                af[mt][2] = lm.y;  af[mt][3] = lm8.y;
            }
#pragma unroll
            for (int mt = 0; mt < 4; mt++)
#pragma unroll
                for (int nt = 0; nt < 4; nt++)
                    mma16(acc[mt][nt], af[mt], bf[nt]);
        }
    }

    // ---- epilogue
    if (HALFOUT) {
        __half* Ch = (__half*)Cv + (size_t)blockIdx.z * sC;
#pragma unroll
        for (int mt = 0; mt < 4; mt++) {
            const int r0 = m0 + wm + mt * 16 + lg;
#pragma unroll
            for (int nt = 0; nt < 4; nt++) {
                const int col = n0 + wn + nt * 8 + (lane & 3) * 2;
                const int pc = (col & ~15) + slot_even(col & 15);
                __half2 v0 = __floats2half2_rn(acc[mt][nt][0] * scale,
                                               acc[mt][nt][1] * scale);
                __half2 v1 = __floats2half2_rn(acc[mt][nt][2] * scale,
                                               acc[mt][nt][3] * scale);
                *reinterpret_cast<__half2*>(Ch + (size_t)r0 * ldc + pc)       = v0;
                *reinterpret_cast<__half2*>(Ch + (size_t)(r0 + 8) * ldc + pc) = v1;
            }
        }
    } else {
        float* Cf = (float*)Cv + (size_t)blockIdx.z * sC;
#pragma unroll
        for (int mt = 0; mt < 4; mt++) {
            const int r0 = m0 + wm + mt * 16 + lg;
#pragma unroll
            for (int nt = 0; nt < 4; nt++) {
                const int col = n0 + wn + nt * 8 + (lane & 3) * 2;
                float bx = 0.f, by = 0.f;
                if (HASBIAS) {
                    float2 bv = *reinterpret_cast<const float2*>(bias + col);
                    bx = bv.x; by = bv.y;
                }
                float2 v0 = make_float2(acc[mt][nt][0] * scale + bx,
                                        acc[mt][nt][1] * scale + by);
                float2 v1 = make_float2(acc[mt][nt][2] * scale + bx,
                                        acc[mt][nt][3] * scale + by);
                *reinterpret_cast<float2*>(Cf + (size_t)r0 * ldc + col)       = v0;
                *reinterpret_cast<float2*>(Cf + (size_t)(r0 + 8) * ldc + col) = v1;
            }
        }
    }
}

// ---------------------------------------------------------------------------
// Pack: fp32 -> fp16 with k-permutation (float4 per thread).
// ---------------------------------------------------------------------------
__global__ void pack_kernel(const float* __restrict__ in, __half* __restrict__ out,
                            size_t n4, int ld)
{
    size_t i = (size_t)blockIdx.x * blockDim.x + threadIdx.x;
    if (i >= n4) return;
    const size_t el = i * 4;
    const int c = (int)(el % ld);
    const size_t r = el / ld;
    const float4 q = *reinterpret_cast<const float4*>(in + el);
    __half* ob = out + r * (size_t)ld + (c & ~15);
    const int e = c & 15;
    *reinterpret_cast<__half2*>(ob + slot_even(e))     = __floats2half2_rn(q.x, q.y);
    *reinterpret_cast<__half2*>(ob + slot_even(e + 2)) = __floats2half2_rn(q.z, q.w);
}

// ---------------------------------------------------------------------------
// Masked causal softmax: reads fp32 scores, writes fp16 permuted attn.
// ---------------------------------------------------------------------------
__global__ void softmax_kernel(float* __restrict__ scores,
                               __half* __restrict__ attn,
                               const int* __restrict__ mask)
{
    const int t = blockIdx.x;
    const int b = blockIdx.y;
    float* row = scores + ((size_t)b * TT + t) * TT;
    __half* arow = attn + ((size_t)b * TT + t) * TT;
    const int* mrow = mask + b * TT;
    const int tid = threadIdx.x;

    __shared__ float red[256];

    float mx = -INFINITY;
    for (int s = tid; s <= t; s += 256)
        if (mrow[s]) mx = fmaxf(mx, row[s]);
    red[tid] = mx;
    __syncthreads();
    for (int w = 128; w > 0; w >>= 1) {
        if (tid < w) red[tid] = fmaxf(red[tid], red[tid + w]);
        __syncthreads();
    }
    mx = red[0];
    __syncthreads();

    float sum = 0.f;
    for (int s = tid; s < TT; s += 256) {
        float val = 0.f;
        if (s <= t && mrow[s]) {
            val = expf(row[s] - mx);
            sum += val;
        }
        row[s] = val;
    }
    red[tid] = sum;
    __syncthreads();
    for (int w = 128; w > 0; w >>= 1) {
        if (tid < w) red[tid] += red[tid + w];
        __syncthreads();
    }
    sum = red[0];
    __syncthreads();

    const float inv = (sum > 0.f) ? 1.f / sum : 0.f;
    for (int s = tid; s < TT; s += 256) {
        const int e = s & 15;
        const int ps = (s & ~15) + (e & 1) + (((e >> 1) & 3) << 2) + (((e >> 3) & 1) << 1);
        arow[ps] = __float2half(row[s] * inv);
    }
}

// ---------------------------------------------------------------------------
// Launch
// ---------------------------------------------------------------------------
static inline int cdiv_sz(size_t a, int b) { return (int)((a + b - 1) / b); }

extern "C" void kernel_launch(void* const* d_in, const int* in_sizes, int n_in,
                              void* d_out, int out_size)
{
    const float* h    = (const float*)d_in[0];
    const float* e    = (const float*)d_in[1];
    const int*   mask = (const int*)  d_in[2];
    const float* Wq   = (const float*)d_in[3];
    const float* Wk   = (const float*)d_in[4];
    const float* Wv   = (const float*)d_in[5];
    const float* Wout = (const float*)d_in[6];
    const float* bout = (const float*)d_in[7];
    float* out = (float*)d_out;

    __half *hp, *ep, *wqp, *wkp, *wvp, *wop, *q, *k, *vT, *ctx, *attn;
    float *sc;
    cudaGetSymbolAddress((void**)&hp,   g_hp);
    cudaGetSymbolAddress((void**)&ep,   g_ep);
    cudaGetSymbolAddress((void**)&wqp,  g_wqp);
    cudaGetSymbolAddress((void**)&wkp,  g_wkp);
    cudaGetSymbolAddress((void**)&wvp,  g_wvp);
    cudaGetSymbolAddress((void**)&wop,  g_wop);
    cudaGetSymbolAddress((void**)&q,    g_q);
    cudaGetSymbolAddress((void**)&k,    g_k);
    cudaGetSymbolAddress((void**)&vT,   g_vT);
    cudaGetSymbolAddress((void**)&ctx,  g_ctx);
    cudaGetSymbolAddress((void**)&attn, g_attn);
    cudaGetSymbolAddress((void**)&sc,   g_scores);

    cudaFuncSetAttribute(tc_nt_kernel<false, false, true>,
                         cudaFuncAttributeMaxDynamicSharedMemorySize, GEMM_SMEM);
    cudaFuncSetAttribute(tc_nt_kernel<true, false, false>,
                         cudaFuncAttributeMaxDynamicSharedMemorySize, GEMM_SMEM);
    cudaFuncSetAttribute(tc_nt_kernel<false, true, false>,
                         cudaFuncAttributeMaxDynamicSharedMemorySize, GEMM_SMEM);

    const float att_scale = 1.0f / 32.0f;   // KV^-0.5
    const int PT = 256;

    // 0) pack inputs + weights (fp16 + permute)
    pack_kernel<<<cdiv_sz((size_t)MTOT*HID/4, PT), PT>>>(h,    hp,  (size_t)MTOT*HID/4, HID);
    pack_kernel<<<cdiv_sz((size_t)MTOT*HID/4, PT), PT>>>(e,    ep,  (size_t)MTOT*HID/4, HID);
    pack_kernel<<<cdiv_sz((size_t)KVD*HID/4,  PT), PT>>>(Wq,   wqp, (size_t)KVD*HID/4,  HID);
    pack_kernel<<<cdiv_sz((size_t)KVD*HID/4,  PT), PT>>>(Wk,   wkp, (size_t)KVD*HID/4,  HID);
    pack_kernel<<<cdiv_sz((size_t)KVD*HID/4,  PT), PT>>>(Wv,   wvp, (size_t)KVD*HID/4,  HID);
    pack_kernel<<<cdiv_sz((size_t)VOC*KVD/4,  PT), PT>>>(Wout, wop, (size_t)VOC*KVD/4,  KVD);

    // 1) q = h @ Wq^T, k = e @ Wk^T  (fp16-permuted outputs)
    {
        dim3 grid(MTOT / BM, KVD / BN, 1);
        tc_nt_kernel<false, false, true><<<grid, 256, GEMM_SMEM>>>(
            hp, wqp, q, nullptr, MTOT, KVD, HID, HID, HID, KVD, 1.f, 0, 0, 0, 0);
        tc_nt_kernel<false, false, true><<<grid, 256, GEMM_SMEM>>>(
            ep, wkp, k, nullptr, MTOT, KVD, HID, HID, HID, KVD, 1.f, 0, 0, 0, 0);
    }

    // 1b) vT = Wv @ e^T : [KVD, MTOT]
    {
        dim3 grid(KVD / BM, MTOT / BN, 1);
        tc_nt_kernel<false, false, true><<<grid, 256, GEMM_SMEM>>>(
            wvp, ep, vT, nullptr, KVD, MTOT, HID, HID, HID, MTOT, 1.f, 0, 0, 0, 0);
    }

    // 2) scores = scale * q @ k^T (causal block-skip), fp32 out, per batch
    {
        dim3 grid(TT / BM, TT / BN, BBATCH);
        tc_nt_kernel<true, false, false><<<grid, 256, GEMM_SMEM>>>(
            q, k, sc, nullptr, TT, TT, KVD, KVD, KVD, TT, att_scale,
            (size_t)TT * KVD, (size_t)TT * KVD, (size_t)TT * TT, 0);
    }

    // 3) softmax -> fp16 permuted attn
    {
        dim3 grid(TT, BBATCH);
        softmax_kernel<<<grid, 256>>>(sc, attn, mask);
    }

    // 4) ctx = attn @ V = NT(attn, vT), K clamped by causality
    {
        dim3 grid(TT / BM, KVD / BN, BBATCH);
        tc_nt_kernel<false, false, true><<<grid, 256, GEMM_SMEM>>>(
            attn, vT, ctx, nullptr, TT, KVD, TT, TT, MTOT, KVD, 1.f,
            (size_t)TT * TT, (size_t)TT, (size_t)TT * KVD, 1);
    }

    // 5) out = ctx @ Wout^T + bout  (m-fast grid: ctx stays L2-resident)
    {
        dim3 grid(MTOT / BM, VOC / BN, 1);
        tc_nt_kernel<false, true, false><<<grid, 256, GEMM_SMEM>>>(
            ctx, wop, out, bout, MTOT, VOC, KVD, KVD, KVD, VOC, 1.f, 0, 0, 0, 0);
    }
}